// round 5
// baseline (speedup 1.0000x reference)
#include <cuda_runtime.h>

#define NN 100000
#define NE 1600000
#define NF 128
#define KCH 4
#define PD 32
#define HID 128
#define TN 64

// ---- device-global scratch (no allocs allowed) ----
__device__ float g_C[(size_t)NN * HID];   // c[n][k*32+p]
__device__ float g_acol[NN * 4];
__device__ float g_arow[NN * 4];
__device__ float g_Wbig[NF * HID];        // Wbig[f][k*32+p]
__device__ float g_bcomb[HID];

// ---------------------------------------------------------------------------
// Kernel 0: Wbig = Wlin @ Wconv per channel (folded), bcomb = blin @ Wconv
// grid = NF+1 blocks (last block computes bcomb), 128 threads
// ---------------------------------------------------------------------------
__global__ void k_combine(const float* __restrict__ Wlin,
                          const float* __restrict__ blin,
                          const float* __restrict__ Wconv) {
    int f  = blockIdx.x;
    int kp = threadIdx.x;          // 0..127
    int k = kp >> 5, p = kp & 31;
    float s = 0.f;
    const float* wc = Wconv + (size_t)k * PD * PD + p;
    if (f < NF) {
        const float* wl = Wlin + ((size_t)k * NF + f) * PD;
#pragma unroll
        for (int q = 0; q < PD; q++) s = fmaf(wl[q], wc[q * PD], s);
        g_Wbig[f * HID + kp] = s;
    } else {
        const float* bl = blin + k * PD;
#pragma unroll
        for (int q = 0; q < PD; q++) s = fmaf(bl[q], wc[q * PD], s);
        g_bcomb[kp] = s;
    }
}

// ---------------------------------------------------------------------------
// Kernel 1: fused  C = x @ Wbig + bcomb  AND  acol/arow = x @ aW1 halves.
// block = 256 threads, tile = 64 nodes x 128 cols; thread = 8 nodes x 4 cols.
// The assigner projection rides on the same shared x-tile, saving a second
// full DRAM pass over x (51 MB) and one kernel launch.
// ---------------------------------------------------------------------------
__global__ __launch_bounds__(256) void k_gemm(const float* __restrict__ x,
                                              const float* __restrict__ aW1) {
    __shared__ float xs[NF][TN + 1];   // k-major x tile, +1 pad
    const int n0 = blockIdx.x * TN;
    const int tid = threadIdx.x;

    // cooperative load: 64 nodes x 32 float4 each
    for (int i = tid; i < TN * 32; i += 256) {
        int n = i >> 5;
        int f4 = i & 31;
        float4 v = make_float4(0.f, 0.f, 0.f, 0.f);
        int gn = n0 + n;
        if (gn < NN) v = __ldg((const float4*)(x + (size_t)gn * NF + f4 * 4));
        xs[f4 * 4 + 0][n] = v.x;
        xs[f4 * 4 + 1][n] = v.y;
        xs[f4 * 4 + 2][n] = v.z;
        xs[f4 * 4 + 3][n] = v.w;
    }
    __syncthreads();

    const int tx = tid & 31;       // column group
    const int ty = tid >> 5;       // node group (0..7)
    const int c0 = tx * 4;
    float acc[8][4];
#pragma unroll
    for (int j = 0; j < 8; j++) { acc[j][0] = acc[j][1] = acc[j][2] = acc[j][3] = 0.f; }

    const float4* W4 = (const float4*)g_Wbig;
#pragma unroll 4
    for (int k = 0; k < NF; k++) {
        float4 w = __ldg(&W4[k * 32 + tx]);
#pragma unroll
        for (int j = 0; j < 8; j++) {
            float xv = xs[k][ty * 8 + j];
            acc[j][0] = fmaf(xv, w.x, acc[j][0]);
            acc[j][1] = fmaf(xv, w.y, acc[j][1]);
            acc[j][2] = fmaf(xv, w.z, acc[j][2]);
            acc[j][3] = fmaf(xv, w.w, acc[j][3]);
        }
    }

    float4 bc = __ldg(&((const float4*)g_bcomb)[tx]);
#pragma unroll
    for (int j = 0; j < 8; j++) {
        int n = n0 + ty * 8 + j;
        if (n < NN) {
            float4 o = make_float4(acc[j][0] + bc.x, acc[j][1] + bc.y,
                                   acc[j][2] + bc.z, acc[j][3] + bc.w);
            *(float4*)(g_C + (size_t)n * HID + c0) = o;
        }
    }

    // ---- assigner projections from the same x tile ----
    // Warp ty owns nodes [ty*8, ty*8+8). Lane tx covers features
    // [tx*4, tx*4+4); full-warp xor-shuffle sums all 128 features.
#pragma unroll
    for (int node_in_ty = 0; node_in_ty < 8; node_in_ty++) {
        int n = ty * 8 + node_in_ty;
        int gn = n0 + n;
        float pc[4] = {0.f, 0.f, 0.f, 0.f};
        float pr[4] = {0.f, 0.f, 0.f, 0.f};
        int f0 = tx * 4;
#pragma unroll
        for (int j = 0; j < 4; j++) {
            float xj = xs[f0 + j][n];
            float4 wc = __ldg((const float4*)(aW1 + (f0 + j) * 4));
            float4 wr = __ldg((const float4*)(aW1 + (128 + f0 + j) * 4));
            pc[0] = fmaf(xj, wc.x, pc[0]); pc[1] = fmaf(xj, wc.y, pc[1]);
            pc[2] = fmaf(xj, wc.z, pc[2]); pc[3] = fmaf(xj, wc.w, pc[3]);
            pr[0] = fmaf(xj, wr.x, pr[0]); pr[1] = fmaf(xj, wr.y, pr[1]);
            pr[2] = fmaf(xj, wr.z, pr[2]); pr[3] = fmaf(xj, wr.w, pr[3]);
        }
#pragma unroll
        for (int o = 16; o > 0; o >>= 1) {
#pragma unroll
            for (int q = 0; q < 4; q++) {
                pc[q] += __shfl_xor_sync(0xffffffffu, pc[q], o);
                pr[q] += __shfl_xor_sync(0xffffffffu, pr[q], o);
            }
        }
        if (tx == 0 && gn < NN) {
            *(float4*)(g_acol + gn * 4) = make_float4(pc[0], pc[1], pc[2], pc[3]);
            *(float4*)(g_arow + gn * 4) = make_float4(pr[0], pr[1], pr[2], pr[3]);
        }
    }
}

// ---------------------------------------------------------------------------
// Kernel 2: fused edge-weight softmax + weighted scatter-add (vector RED).
// Warp per edge, blocked contiguous span per warp. Software pipeline now
// prefetches the ENTIRE next-edge working set (indices, assigner float4s,
// AND the 512B g_C row) before the current edge's compute, so no L2 round
// trip remains on the per-iteration critical path — only ALU + RED issue.
// ---------------------------------------------------------------------------
__global__ __launch_bounds__(256) void k_agg(const int* __restrict__ erow,
                                             const int* __restrict__ ecol,
                                             const float* __restrict__ aW2,
                                             const float* __restrict__ ab1,
                                             const float* __restrict__ ab2,
                                             float* __restrict__ out) {
    const int lane = threadIdx.x & 31;
    const int k = lane >> 3;       // channel for this lane's float4
    const int warp = (blockIdx.x * blockDim.x + threadIdx.x) >> 5;
    const int nwarps = (gridDim.x * blockDim.x) >> 5;

    // contiguous span for this warp
    const int per = (NE + nwarps - 1) / nwarps;
    const int e_beg = warp * per;
    const int e_end = (e_beg + per < NE) ? (e_beg + per) : NE;
    if (e_beg >= e_end) return;

    // hoist tiny params into registers
    float w2[16];
#pragma unroll
    for (int i = 0; i < 16; i++) w2[i] = __ldg(aW2 + i);
    float b1x = __ldg(ab1 + 0), b1y = __ldg(ab1 + 1), b1z = __ldg(ab1 + 2), b1w = __ldg(ab1 + 3);
    float b2x = __ldg(ab2 + 0), b2y = __ldg(ab2 + 1), b2z = __ldg(ab2 + 2), b2w = __ldg(ab2 + 3);

    // ---- pipeline prologue: full working set for the first edge ----
    int r  = __ldg(erow + e_beg);
    int cc = __ldg(ecol + e_beg);
    float4 ac = __ldg((const float4*)(g_acol + cc * 4));
    float4 ar = __ldg((const float4*)(g_arow + r * 4));
    float4 cv = __ldg((const float4*)(g_C + (size_t)cc * HID + lane * 4));

    for (int e = e_beg; e < e_end; e++) {
        // current-edge state
        const int r_c = r;
        const float4 ac_c = ac, ar_c = ar, cv_c = cv;

        // prefetch ENTIRE next-edge working set before compute
        if (e + 1 < e_end) {
            r  = __ldg(erow + e + 1);
            cc = __ldg(ecol + e + 1);
            ac = __ldg((const float4*)(g_acol + cc * 4));
            ar = __ldg((const float4*)(g_arow + r * 4));
            cv = __ldg((const float4*)(g_C + (size_t)cc * HID + lane * 4));
        }

        float h0 = ac_c.x + ar_c.x + b1x;
        float h1 = ac_c.y + ar_c.y + b1y;
        float h2 = ac_c.z + ar_c.z + b1z;
        float h3 = ac_c.w + ar_c.w + b1w;

        float t0 = fmaf(h0, w2[0], fmaf(h1, w2[4], fmaf(h2, w2[8],  fmaf(h3, w2[12], b2x))));
        float t1 = fmaf(h0, w2[1], fmaf(h1, w2[5], fmaf(h2, w2[9],  fmaf(h3, w2[13], b2y))));
        float t2 = fmaf(h0, w2[2], fmaf(h1, w2[6], fmaf(h2, w2[10], fmaf(h3, w2[14], b2z))));
        float t3 = fmaf(h0, w2[3], fmaf(h1, w2[7], fmaf(h2, w2[11], fmaf(h3, w2[15], b2w))));

        float m = fmaxf(fmaxf(t0, t1), fmaxf(t2, t3));
        float e0 = __expf(t0 - m), e1 = __expf(t1 - m);
        float e2 = __expf(t2 - m), e3 = __expf(t3 - m);
        float inv = 1.f / (e0 + e1 + e2 + e3);
        float wk = ((k == 0) ? e0 : (k == 1) ? e1 : (k == 2) ? e2 : e3) * inv;

        float* dst = out + (size_t)r_c * HID + lane * 4;
        asm volatile("red.global.add.v4.f32 [%0], {%1, %2, %3, %4};"
                     :: "l"(dst), "f"(cv_c.x * wk), "f"(cv_c.y * wk),
                        "f"(cv_c.z * wk), "f"(cv_c.w * wk)
                     : "memory");
    }
}

// ---------------------------------------------------------------------------
// Kernel 3: out += bch; per-channel L2-normalize; logits = h @ Wcls + bcls
// warp per node
// ---------------------------------------------------------------------------
__global__ __launch_bounds__(256) void k_final(const float* __restrict__ bch,
                                               const float* __restrict__ Wcls,
                                               const float* __restrict__ bcls,
                                               float* __restrict__ out) {
    int gw = (blockIdx.x * blockDim.x + threadIdx.x) >> 5;
    int lane = threadIdx.x & 31;
    if (gw >= NN) return;

    float* row = out + (size_t)gw * HID + lane * 4;
    float4 v = *(float4*)row;
    float4 b = __ldg((const float4*)(bch + lane * 4));
    v.x += b.x; v.y += b.y; v.z += b.z; v.w += b.w;

    float ss = v.x * v.x + v.y * v.y + v.z * v.z + v.w * v.w;
    ss += __shfl_xor_sync(0xffffffffu, ss, 1);
    ss += __shfl_xor_sync(0xffffffffu, ss, 2);
    ss += __shfl_xor_sync(0xffffffffu, ss, 4);   // 8-lane group = one channel (P=32)
    float invn = 1.f / fmaxf(sqrtf(ss), 1e-12f);
    v.x *= invn; v.y *= invn; v.z *= invn; v.w *= invn;
    *(float4*)row = v;

    float4 wc = __ldg((const float4*)(Wcls + lane * 4));
    float p = v.x * wc.x + v.y * wc.y + v.z * wc.z + v.w * wc.w;
#pragma unroll
    for (int o = 16; o > 0; o >>= 1) p += __shfl_xor_sync(0xffffffffu, p, o);
    if (lane == 0) out[(size_t)NN * HID + gw] = p + __ldg(bcls);
}

// ---------------------------------------------------------------------------
extern "C" void kernel_launch(void* const* d_in, const int* in_sizes, int n_in,
                              void* d_out, int out_size) {
    const float* x     = (const float*)d_in[0];
    const int*   erow  = (const int*)  d_in[1];
    const int*   ecol  = (const int*)  d_in[2];
    const float* aW1   = (const float*)d_in[3];
    const float* ab1   = (const float*)d_in[4];
    const float* aW2   = (const float*)d_in[5];
    const float* ab2   = (const float*)d_in[6];
    const float* Wlin  = (const float*)d_in[7];
    const float* blin  = (const float*)d_in[8];
    const float* Wconv = (const float*)d_in[9];
    const float* bch   = (const float*)d_in[10];
    const float* Wcls  = (const float*)d_in[11];
    const float* bcls  = (const float*)d_in[12];
    float* out = (float*)d_out;

    cudaMemsetAsync(out, 0, (size_t)NN * HID * sizeof(float));
    k_combine<<<NF + 1, HID>>>(Wlin, blin, Wconv);
    k_gemm<<<(NN + TN - 1) / TN, 256>>>(x, aW1);
    k_agg<<<2048, 256>>>(erow, ecol, aW2, ab1, ab2, out);
    k_final<<<(NN * 32 + 255) / 256, 256>>>(bch, Wcls, bcls, out);
}